// round 1
// baseline (speedup 1.0000x reference)
#include <cuda_runtime.h>
#include <cuda_bf16.h>
#include <stdint.h>

// Problem dims
#define B_     4096
#define IN_    1024
#define ND_    8192
#define OD_    512
#define DPC_   16
#define KWIN_  819

// -------- device scratch (allowed: __device__ globals, no runtime alloc) -----
__device__ float g_w1m[(size_t)ND_ * IN_];   // 32 MB masked weights
__device__ float g_h[(size_t)B_ * ND_];      // 128 MB hidden activations
__device__ int   g_mask_mode;                // 0=u8, 1=f32, 2=i32, 3=bf16

// =============== kernel 0: probe mask dtype =================================
// Read only the first 4096 u32 words (16 KB) — safe under every interpretation
// (smallest candidate is u8: 8 MB). Classify the bit pattern.
__global__ void probe_mask_kernel(const unsigned int* __restrict__ m) {
    __shared__ int f_bf16, f_f32, f_u8;
    if (threadIdx.x == 0) { f_bf16 = 0; f_f32 = 0; f_u8 = 0; }
    __syncthreads();
    int lb = 0, lf = 0, lu = 0;
    for (int i = threadIdx.x; i < 4096; i += blockDim.x) {
        unsigned w = m[i];
        if (w == 0x00003F80u || w == 0x3F803F80u)       lb = 1;  // bf16 1.0 patterns
        else if (w == 0x3F800000u)                      lf = 1;  // f32 1.0
        else if (w > 1u && (w & 0xFEFEFEFEu) == 0u)     lu = 1;  // packed u8 0/1
    }
    if (lb) atomicOr(&f_bf16, 1);
    if (lf) atomicOr(&f_f32, 1);
    if (lu) atomicOr(&f_u8, 1);
    __syncthreads();
    if (threadIdx.x == 0)
        g_mask_mode = f_bf16 ? 3 : (f_f32 ? 1 : (f_u8 ? 0 : 2));
}

// =============== kernel 1: w1m = w1 * mask ==================================
__global__ void apply_mask_kernel(const float* __restrict__ w1,
                                  const void* __restrict__ mask) {
    const int n4 = (ND_ * IN_) / 4;
    int i = blockIdx.x * blockDim.x + threadIdx.x;
    if (i >= n4) return;
    int mode = g_mask_mode;
    float4 w = ((const float4*)w1)[i];
    bool m0, m1, m2, m3;
    if (mode == 0) {
        uchar4 mm = ((const uchar4*)mask)[i];
        m0 = mm.x; m1 = mm.y; m2 = mm.z; m3 = mm.w;
    } else if (mode == 1) {
        float4 mm = ((const float4*)mask)[i];
        m0 = mm.x != 0.f; m1 = mm.y != 0.f; m2 = mm.z != 0.f; m3 = mm.w != 0.f;
    } else if (mode == 2) {
        int4 mm = ((const int4*)mask)[i];
        m0 = mm.x != 0; m1 = mm.y != 0; m2 = mm.z != 0; m3 = mm.w != 0;
    } else {
        const __nv_bfloat16* mp = ((const __nv_bfloat16*)mask) + (size_t)i * 4;
        m0 = __bfloat162float(mp[0]) != 0.f; m1 = __bfloat162float(mp[1]) != 0.f;
        m2 = __bfloat162float(mp[2]) != 0.f; m3 = __bfloat162float(mp[3]) != 0.f;
    }
    w.x = m0 ? w.x : 0.f; w.y = m1 ? w.y : 0.f;
    w.z = m2 ? w.z : 0.f; w.w = m3 ? w.w : 0.f;
    ((float4*)g_w1m)[i] = w;
}

// =============== kernel 2: h = x @ w1m^T + b1 (fp32 SIMT GEMM) ==============
// C[4096x8192] = A[4096x1024] * B[8192x1024]^T, both K-contiguous (NT gemm).
// 128x128 tile, KT=16, 256 threads, 8x8 register tile per thread.
#define MT 128
#define NT 128
#define KT 16
#define SPITCH 136   // 136 % 32 == 8 -> conflict-free transposed stores

__global__ void __launch_bounds__(256, 2)
gemm_masked_kernel(const float* __restrict__ A,
                   const float* __restrict__ b1,
                   float* __restrict__ C) {
    __shared__ float As[KT][SPITCH];
    __shared__ float Bs[KT][SPITCH];

    const float* __restrict__ Bm = g_w1m;

    // CTA swizzle: groups of (8 N-tiles x 32 M-tiles) = 256 CTAs per group so a
    // wave touches all of A (16 MB) + an 8-tile B panel (4 MB) -> L2-resident.
    int bid   = blockIdx.x;
    int ing   = bid & 255;
    int ntile = (bid >> 8) * 8 + (ing & 7);
    int mtile = ing >> 3;
    int m0 = mtile * MT, n0 = ntile * NT;

    int tid = threadIdx.x;
    int tx = tid & 15;        // n direction (16)
    int ty = tid >> 4;        // m direction (16)

    float acc[8][8];
#pragma unroll
    for (int i = 0; i < 8; i++)
#pragma unroll
        for (int j = 0; j < 8; j++) acc[i][j] = 0.f;

    for (int k0 = 0; k0 < IN_; k0 += KT) {
        // load A and B tiles (each 128 rows x 16 k), transposed into smem
#pragma unroll
        for (int it = 0; it < 2; it++) {
            int v  = tid + it * 256;      // 0..511 float4 slots
            int m  = v >> 2;              // 0..127
            int k4 = v & 3;               // 0..3
            float4 a = *(const float4*)&A [(size_t)(m0 + m) * IN_ + k0 + k4 * 4];
            float4 b = *(const float4*)&Bm[(size_t)(n0 + m) * IN_ + k0 + k4 * 4];
            As[k4 * 4 + 0][m] = a.x; As[k4 * 4 + 1][m] = a.y;
            As[k4 * 4 + 2][m] = a.z; As[k4 * 4 + 3][m] = a.w;
            Bs[k4 * 4 + 0][m] = b.x; Bs[k4 * 4 + 1][m] = b.y;
            Bs[k4 * 4 + 2][m] = b.z; Bs[k4 * 4 + 3][m] = b.w;
        }
        __syncthreads();

#pragma unroll
        for (int k = 0; k < KT; k++) {
            float af[8], bf[8];
            *(float4*)&af[0] = *(float4*)&As[k][ty * 8];
            *(float4*)&af[4] = *(float4*)&As[k][ty * 8 + 4];
            *(float4*)&bf[0] = *(float4*)&Bs[k][tx * 8];
            *(float4*)&bf[4] = *(float4*)&Bs[k][tx * 8 + 4];
#pragma unroll
            for (int i = 0; i < 8; i++)
#pragma unroll
                for (int j = 0; j < 8; j++)
                    acc[i][j] += af[i] * bf[j];
        }
        __syncthreads();
    }

    // epilogue: + b1, store
    float bias[8];
    *(float4*)&bias[0] = *(const float4*)&b1[n0 + tx * 8];
    *(float4*)&bias[4] = *(const float4*)&b1[n0 + tx * 8 + 4];
#pragma unroll
    for (int i = 0; i < 8; i++) {
        size_t row = (size_t)(m0 + ty * 8 + i);
        float4 v0, v1;
        v0.x = acc[i][0] + bias[0]; v0.y = acc[i][1] + bias[1];
        v0.z = acc[i][2] + bias[2]; v0.w = acc[i][3] + bias[3];
        v1.x = acc[i][4] + bias[4]; v1.y = acc[i][5] + bias[5];
        v1.z = acc[i][6] + bias[6]; v1.w = acc[i][7] + bias[7];
        *(float4*)&C[row * ND_ + n0 + tx * 8]     = v0;
        *(float4*)&C[row * ND_ + n0 + tx * 8 + 4] = v1;
    }
}

// =============== kernel 3: per-row exact top-k threshold + output ===========
// Monotone float->u32 key: larger float <=> larger unsigned key.
__device__ __forceinline__ unsigned fkey(float f) {
    unsigned u = __float_as_uint(f);
    return (u & 0x80000000u) ? ~u : (u | 0x80000000u);
}

__global__ void __launch_bounds__(256)
select_output_kernel(const float* __restrict__ H,
                     const float* __restrict__ w2,
                     const float* __restrict__ b2,
                     float* __restrict__ out) {
    __shared__ float hs[ND_];
    __shared__ unsigned int hist[256];
    __shared__ unsigned int s_prefix;
    __shared__ int s_kk;

    int b = blockIdx.x;
    int tid = threadIdx.x;
    const float* hrow = H + (size_t)b * ND_;

    // stage full h row (32 KB)
    for (int i = tid; i < ND_ / 4; i += 256)
        ((float4*)hs)[i] = ((const float4*)hrow)[i];
    __syncthreads();

    // 4-pass radix select: exact key of the 819th-largest value
    unsigned prefix = 0;
    int kk = KWIN_;
#pragma unroll 1
    for (int pass = 0; pass < 4; pass++) {
        int shift = 24 - pass * 8;
        hist[tid] = 0;
        __syncthreads();
        for (int i = tid; i < ND_; i += 256) {
            unsigned u = fkey(hs[i]);
            bool cand = (pass == 0) || ((u >> (shift + 8)) == (prefix >> (shift + 8)));
            if (cand) atomicAdd(&hist[(u >> shift) & 255u], 1u);
        }
        __syncthreads();
        if (tid == 0) {
            unsigned cum = 0; int bin = 255;
            for (; bin > 0; bin--) {
                unsigned c = hist[bin];
                if (cum + c >= (unsigned)kk) break;
                cum += c;
            }
            s_prefix = prefix | ((unsigned)bin << shift);
            s_kk = kk - (int)cum;
        }
        __syncthreads();
        prefix = s_prefix;
        kk = s_kk;
        __syncthreads();
    }
    unsigned thr_key = prefix;   // keep h iff fkey(h) >= thr_key (exact value of k-th)

    // block-diagonal contraction: out[b][o] = b2[o] + sum_d kept(h[o*16+d]) * w2[o][o*16+d]
    for (int o = tid; o < OD_; o += 256) {
        const float* w2p = w2 + (size_t)o * (DPC_ * OD_) + o * DPC_;  // 64B aligned
        float w[16];
        *(float4*)&w[0]  = __ldg((const float4*)(w2p + 0));
        *(float4*)&w[4]  = __ldg((const float4*)(w2p + 4));
        *(float4*)&w[8]  = __ldg((const float4*)(w2p + 8));
        *(float4*)&w[12] = __ldg((const float4*)(w2p + 12));
        float s = __ldg(&b2[o]);
#pragma unroll
        for (int d = 0; d < DPC_; d++) {
            float h = hs[o * DPC_ + d];
            if (fkey(h) >= thr_key) s += h * w[d];
        }
        out[(size_t)b * OD_ + o] = s;
    }
}

// =============== launcher ====================================================
extern "C" void kernel_launch(void* const* d_in, const int* in_sizes, int n_in,
                              void* d_out, int out_size) {
    const float* x    = (const float*)d_in[0];   // [4096,1024]
    const float* w1   = (const float*)d_in[1];   // [8192,1024]
    const float* b1   = (const float*)d_in[2];   // [8192]
    const void*  msk  = d_in[3];                 // [8192,1024] (dtype probed)
    const float* w2   = (const float*)d_in[4];   // [512,8192]
    const float* b2   = (const float*)d_in[5];   // [512]
    float* out = (float*)d_out;                  // [4096,512]

    float* w1m_ptr; cudaGetSymbolAddress((void**)&w1m_ptr, g_w1m);
    float* h_ptr;   cudaGetSymbolAddress((void**)&h_ptr,   g_h);

    probe_mask_kernel<<<1, 256>>>((const unsigned int*)msk);
    apply_mask_kernel<<<(ND_ * IN_ / 4 + 255) / 256, 256>>>(w1, msk);
    gemm_masked_kernel<<<(B_ / MT) * (ND_ / NT), 256>>>(x, b1, h_ptr);
    select_output_kernel<<<B_, 256>>>(h_ptr, w2, b2, out);
}